// round 17
// baseline (speedup 1.0000x reference)
#include <cuda_runtime.h>
#include <cuda_bf16.h>
#include <cstdint>

#define D 200
#define NREL 474
#define NTAB 948
#define VMAX 100000
#define EMAX 1000000
#define THREADS 512
#define NCTA 148
#define TILE 32            // GEMM rows per CTA tile
#define PITCH 216          // bf16 row pitch (conflict-free ldmatrix)
#define KROWS 208          // padded K
#define CHUNK 676          // ceil(VMAX/NCTA)

typedef unsigned long long ull;

// ---- device scratch (no cudaMalloc allowed) ----
__device__ __align__(16) float g_Mtab[NTAB * D];
__device__ __align__(16) float g_Weff[D * D];
__device__ __align__(16) float2 g_sedge[EMAX];
__device__ int g_cnt[VMAX];
__device__ int g_off[VMAX + 1];
__device__ int g_cursor[VMAX];
__device__ int g_bsum[NCTA];
__device__ int g_boff[NCTA];
__device__ float g_sum[D], g_sumsq[D];
__device__ unsigned g_barGen, g_barCnt;

__device__ __forceinline__ uint32_t smem_u32(const void* p) {
    uint32_t a;
    asm("{ .reg .u64 t; cvta.to.shared.u64 t, %1; cvt.u32.u64 %0, t; }"
        : "=r"(a) : "l"(p));
    return a;
}
__device__ __forceinline__ void ldsm_x4(uint32_t& r0, uint32_t& r1,
                                        uint32_t& r2, uint32_t& r3, uint32_t a) {
    asm volatile("ldmatrix.sync.aligned.m8n8.x4.shared.b16 {%0,%1,%2,%3}, [%4];"
                 : "=r"(r0), "=r"(r1), "=r"(r2), "=r"(r3) : "r"(a));
}
__device__ __forceinline__ void ldsm_x2t(uint32_t& r0, uint32_t& r1, uint32_t a) {
    asm volatile("ldmatrix.sync.aligned.m8n8.x2.trans.shared.b16 {%0,%1}, [%2];"
                 : "=r"(r0), "=r"(r1) : "r"(a));
}
__device__ __forceinline__ void mma_bf16(float& c0, float& c1, float& c2, float& c3,
                                         uint32_t a0, uint32_t a1, uint32_t a2,
                                         uint32_t a3, uint32_t b0, uint32_t b1) {
    asm volatile(
        "mma.sync.aligned.m16n8k16.row.col.f32.bf16.bf16.f32 "
        "{%0,%1,%2,%3},{%4,%5,%6,%7},{%8,%9},{%0,%1,%2,%3};"
        : "+f"(c0), "+f"(c1), "+f"(c2), "+f"(c3)
        : "r"(a0), "r"(a1), "r"(a2), "r"(a3), "r"(b0), "r"(b1));
}

// ---- generation grid barrier (all 148 CTAs co-resident) ----
__device__ __forceinline__ void grid_bar() {
    __syncthreads();
    if (threadIdx.x == 0) {
        unsigned gen = *(volatile unsigned*)&g_barGen;
        __threadfence();
        if (atomicAdd(&g_barCnt, 1u) == NCTA - 1) {
            g_barCnt = 0;
            __threadfence();
            atomicExch(&g_barGen, gen + 1);
        } else {
            while (*(volatile unsigned*)&g_barGen == gen) __nanosleep(32);
        }
    }
    __syncthreads();
    __threadfence();
}

// ============================================================================
__global__ void __launch_bounds__(THREADS, 1)
mega_kernel(const float* __restrict__ x,
            const float* __restrict__ rel_repr,
            const float* __restrict__ edge_norm,
            const float* __restrict__ in_w,
            const float* __restrict__ out_w,
            const float* __restrict__ loop_w,
            const float* __restrict__ w_rel,
            const float* __restrict__ loop_rel,
            const float* __restrict__ bias,
            const float* __restrict__ bn_w,
            const float* __restrict__ bn_b,
            const int* __restrict__ edge_type,
            const int* __restrict__ dst,
            float* __restrict__ out, int V, int E) {
    extern __shared__ float dynF[];
    __shared__ int   ism[THREADS];
    __shared__ int   s2[256];
    __shared__ float fred[THREADS];
    __shared__ float rs[D];

    const int tid  = threadIdx.x;
    const int cta  = blockIdx.x;
    const int lane = tid & 31;
    const int team = tid >> 5;               // 16 warps
    const bool alane = (lane < 25);
    const int halfE = E / 2;
    float* rel_out = out + (size_t)V * D;
    float* xsF = dynF;                       // prep scratch (phase 3 only)

    // ---------------- phase 0: zero ----------------
    for (int i = cta * THREADS + tid; i < V; i += NCTA * THREADS) g_cnt[i] = 0;
    if (cta == 0 && tid < D) { g_sum[tid] = 0.f; g_sumsq[tid] = 0.f; }
    grid_bar();

    // ---------------- phase 1: histogram of dst ----------------
    for (int e = cta * THREADS + tid; e < E; e += NCTA * THREADS)
        atomicAdd(&g_cnt[dst[e]], 1);
    grid_bar();

    // ---------------- phase 2: scan ----------------
    const int c0 = cta * CHUNK;
    int i0 = c0 + tid * 2;
    bool v0ok = (tid * 2 < CHUNK) && (i0 < V);
    bool v1ok = (tid * 2 + 1 < CHUNK) && (i0 + 1 < V);
    int ca = v0ok ? g_cnt[i0] : 0;
    int cb = v1ok ? g_cnt[i0 + 1] : 0;
    int local = ca + cb;
    ism[tid] = local;
    __syncthreads();
    for (int s = 1; s < THREADS; s <<= 1) {
        int u = (tid >= s) ? ism[tid - s] : 0;
        __syncthreads();
        ism[tid] += u;
        __syncthreads();
    }
    if (tid == THREADS - 1) g_bsum[cta] = ism[THREADS - 1];
    grid_bar();

    if (cta == 0) {
        int v = (tid < NCTA) ? g_bsum[tid] : 0;
        if (tid < 256) s2[tid] = v;
        __syncthreads();
        for (int s = 1; s < 256; s <<= 1) {
            int u = (tid >= s && tid < 256) ? s2[tid - s] : 0;
            __syncthreads();
            if (tid < 256) s2[tid] += u;
            __syncthreads();
        }
        if (tid < NCTA) g_boff[tid] = s2[tid] - v;
        if (tid == 0) g_off[V] = E;
    }
    grid_bar();

    {
        int base = ism[tid] - local + g_boff[cta];
        if (v0ok) { g_off[i0] = base;          g_cursor[i0] = base; }
        if (v1ok) { g_off[i0 + 1] = base + ca; g_cursor[i0 + 1] = base + ca; }
    }
    grid_bar();

    // ---------------- phase 3: sortscatter + prep ----------------
    for (int e = cta * THREADS + tid; e < E; e += NCTA * THREADS) {
        int v = dst[e];
        int row = edge_type[e] + ((e >= halfE) ? NREL : 0);
        int pos = atomicAdd(&g_cursor[v], 1);
        g_sedge[pos] = make_float2(__int_as_float(row), edge_norm[e]);
    }

    {   // prep: 4 tasks per weight sweep (scratch = xsF)
        const int nb = (NREL + 3) / 4;       // 119
        const int totalB = nb * 2 + (D / 4) + nb;
        for (int bb = cta; bb < totalB; bb += NCTA) {
            if (bb < 2 * nb) {
                int hh = bb / nb;
                int b4 = (bb % nb) * 4;
                const float* W = hh ? out_w : in_w;
                for (int i = tid; i < 4 * D; i += THREADS) {
                    int j = i / D, k = i - j * D;
                    int t = b4 + j;
                    xsF[i] = (t < NREL) ? rel_repr[t * D + k] : 0.f;
                }
                __syncthreads();
                float acc[4] = {0.f, 0.f, 0.f, 0.f};
                if (tid < D) {
                    for (int k = 0; k < D; k++) {
                        float wv = W[k * D + tid];
                        #pragma unroll
                        for (int j = 0; j < 4; j++)
                            acc[j] = fmaf(xsF[j * D + k], wv, acc[j]);
                    }
                }
                float ee[4], inv[4];
                #pragma unroll
                for (int j = 0; j < 4; j++) {
                    fred[tid] = (tid < D) ? acc[j] : -1e30f;
                    __syncthreads();
                    for (int s = 256; s > 0; s >>= 1) {
                        if (tid < s) fred[tid] = fmaxf(fred[tid], fred[tid + s]);
                        __syncthreads();
                    }
                    float mx = fred[0];
                    __syncthreads();
                    ee[j] = (tid < D) ? expf(acc[j] - mx) : 0.f;
                    fred[tid] = ee[j];
                    __syncthreads();
                    for (int s = 256; s > 0; s >>= 1) {
                        if (tid < s) fred[tid] += fred[tid + s];
                        __syncthreads();
                    }
                    inv[j] = 1.f / (fred[0] * 3.f);
                    __syncthreads();
                }
                if (tid < D) {
                    #pragma unroll
                    for (int j = 0; j < 4; j++) {
                        int t = b4 + j;
                        if (t < NREL)
                            g_Mtab[(hh * NREL + t) * D + tid] = ee[j] * inv[j];
                    }
                }
                __syncthreads();
            } else if (bb < 2 * nb + D / 4) {
                int kk0 = (bb - 2 * nb) * 4;
                if (tid < D) rs[tid] = loop_rel[tid];
                __syncthreads();
                if (tid < D) {
                    float acc[4] = {0.f, 0.f, 0.f, 0.f};
                    for (int m = 0; m < D; m++) {
                        float wv = loop_w[m * D + tid];
                        #pragma unroll
                        for (int j = 0; j < 4; j++) {
                            int mm = m + kk0 + j;
                            if (mm >= D) mm -= D;
                            acc[j] = fmaf(rs[mm], wv, acc[j]);
                        }
                    }
                    #pragma unroll
                    for (int j = 0; j < 4; j++)
                        g_Weff[(kk0 + j) * D + tid] = acc[j] * (1.f / 3.f);
                }
                __syncthreads();
            } else {
                int b4 = (bb - 2 * nb - D / 4) * 4;
                for (int i = tid; i < 4 * D; i += THREADS) {
                    int j = i / D, k = i - j * D;
                    int t = b4 + j;
                    xsF[i] = (t < NREL) ? rel_repr[t * D + k] : 0.f;
                }
                __syncthreads();
                if (tid < D) {
                    float acc[4] = {0.f, 0.f, 0.f, 0.f};
                    for (int k = 0; k < D; k++) {
                        float wv = w_rel[k * D + tid];
                        #pragma unroll
                        for (int j = 0; j < 4; j++)
                            acc[j] = fmaf(xsF[j * D + k], wv, acc[j]);
                    }
                    #pragma unroll
                    for (int j = 0; j < 4; j++)
                        if (b4 + j < NREL) rel_out[(b4 + j) * D + tid] = acc[j];
                }
                __syncthreads();
            }
        }
    }
    grid_bar();

    // ======= phase 4: tensor-core GEMM out = x@Weff + bias (bf16 3-pass) =====
    {
        __nv_bfloat16* whi = reinterpret_cast<__nv_bfloat16*>(dynF);
        __nv_bfloat16* wlo = whi + KROWS * PITCH;
        __nv_bfloat16* xhi = wlo + KROWS * PITCH;
        __nv_bfloat16* xlo = xhi + TILE * PITCH;

        for (int i = tid; i < KROWS * PITCH; i += THREADS) {
            int k = i / PITCH, n = i % PITCH;
            float v = (k < D && n < D) ? g_Weff[k * D + n] : 0.f;
            __nv_bfloat16 h = __float2bfloat16(v);
            whi[i] = h;
            wlo[i] = __float2bfloat16(v - __bfloat162float(h));
        }
        __syncthreads();

        const uint32_t whiA = smem_u32(whi);
        const uint32_t wloA = smem_u32(wlo);
        const uint32_t xhiA = smem_u32(xhi);
        const uint32_t xloA = smem_u32(xlo);

        const int rowg = team >> 3;
        const int colg = team & 7;
        const int r0l  = rowg * 16;
        const int a_row = r0l + (lane & 7) + ((lane >> 3) & 1) * 8;
        const int a_k8  = (lane >> 4) * 8;
        const int b_koff = (lane & 7) + ((lane >> 3) & 1) * 8;

        const int gr = lane >> 2;
        const int tc = lane & 3;
        float bi0[4], bi1[4];
        #pragma unroll
        for (int i = 0; i < 4; i++) {
            int nt = colg + 8 * i;
            int col = nt * 8 + tc * 2;
            bi0[i] = (col < D) ? bias[col] : 0.f;
            bi1[i] = (col + 1 < D) ? bias[col + 1] : 0.f;
        }

        const int ntiles = (V + TILE - 1) / TILE;
        for (int tile = cta; tile < ntiles; tile += NCTA) {
            int row0 = tile * TILE;
            __syncthreads();
            for (int i = tid; i < TILE * PITCH; i += THREADS) {
                int r = i / PITCH, k = i % PITCH;
                int vrow = row0 + r;
                float v = (vrow < V && k < D) ? x[(size_t)vrow * D + k] : 0.f;
                __nv_bfloat16 h = __float2bfloat16(v);
                xhi[i] = h;
                xlo[i] = __float2bfloat16(v - __bfloat162float(h));
            }
            __syncthreads();

            float c[4][4];
            #pragma unroll
            for (int i = 0; i < 4; i++)
                #pragma unroll
                for (int q = 0; q < 4; q++) c[i][q] = 0.f;

            #pragma unroll
            for (int pass = 0; pass < 3; pass++) {
                uint32_t ab = (pass == 2) ? xloA : xhiA;
                uint32_t bb = (pass == 1) ? wloA : whiA;
                for (int k0 = 0; k0 < KROWS; k0 += 16) {
                    uint32_t a0, a1, a2, a3;
                    ldsm_x4(a0, a1, a2, a3,
                            ab + (uint32_t)((a_row * PITCH + k0 + a_k8) * 2));
                    #pragma unroll
                    for (int i = 0; i < 4; i++) {
                        int nt = colg + 8 * i;
                        if (nt < 26) {
                            uint32_t b0, b1;
                            ldsm_x2t(b0, b1,
                                     bb + (uint32_t)(((k0 + b_koff) * PITCH + nt * 8) * 2));
                            mma_bf16(c[i][0], c[i][1], c[i][2], c[i][3],
                                     a0, a1, a2, a3, b0, b1);
                        }
                    }
                }
            }

            int vr1 = row0 + r0l + gr;
            int vr2 = vr1 + 8;
            #pragma unroll
            for (int i = 0; i < 4; i++) {
                int nt = colg + 8 * i;
                int col = nt * 8 + tc * 2;
                if (nt < 25) {
                    if (vr1 < V) {
                        float2 st = make_float2(c[i][0] + bi0[i], c[i][1] + bi1[i]);
                        *reinterpret_cast<float2*>(out + (size_t)vr1 * D + col) = st;
                    }
                    if (vr2 < V) {
                        float2 st = make_float2(c[i][2] + bi0[i], c[i][3] + bi1[i]);
                        *reinterpret_cast<float2*>(out + (size_t)vr2 * D + col) = st;
                    }
                }
            }
        }
    }
    grid_bar();

    // ==== phase 5: column-split gather, Mtab chunk in smem + fused BN stats ====
    {
        const int group = cta / 37;          // 4 groups x 37 CTAs
        const int ctaG  = cta - group * 37;
        const int cbase = group * 50;
        float* tab = dynF;                   // 948*50 floats = 189.6 KB

        for (int i = tid; i < NTAB * 50; i += THREADS)
            tab[i] = g_Mtab[(i / 50) * D + cbase + (i % 50)];
        __syncthreads();

        const int lc = (lane < 25) ? lane * 2 : 48;   // 2 cols per lane
        float sS0 = 0.f, sS1 = 0.f, sQ0 = 0.f, sQ1 = 0.f;

        for (int b = ctaG * 16 + team; b * 8 < V; b += 37 * 16) {
            int v0 = b * 8;
            int vhi = (v0 + 8 < V) ? v0 + 8 : V;
            int eend = g_off[vhi];
            int vq = v0 + lane;
            int ofr = (lane < 9) ? g_off[(vq < V) ? vq : V] : 0;
            int bse = 0, winEnd = -1;
            float2 edv = make_float2(0.f, 0.f);
            int rowm = 0;

            #pragma unroll
            for (int r = 0; r < 8; r++) {
                int vrow = v0 + r;
                if (vrow >= V) break;
                int e0 = __shfl_sync(0xffffffffu, ofr, r);
                int e1 = __shfl_sync(0xffffffffu, ofr, r + 1);
                float a0 = 0.f, a1 = 0.f;
                int e = e0;
                while (e < e1) {
                    if (e >= winEnd) {
                        bse = e;
                        edv = (bse + lane < eend) ? g_sedge[bse + lane]
                                                  : make_float2(0.f, 0.f);
                        rowm = __float_as_int(edv.x);
                        winEnd = bse + 32;
                    }
                    int lim = (e1 < winEnd) ? e1 : winEnd;
                    int j = e - bse;
                    int jend = lim - bse;
                    for (; j + 4 <= jend; j += 4) {
                        int r0 = __shfl_sync(0xffffffffu, rowm, j);
                        int r1 = __shfl_sync(0xffffffffu, rowm, j + 1);
                        int r2 = __shfl_sync(0xffffffffu, rowm, j + 2);
                        int r3 = __shfl_sync(0xffffffffu, rowm, j + 3);
                        float n0 = __shfl_sync(0xffffffffu, edv.y, j);
                        float n1 = __shfl_sync(0xffffffffu, edv.y, j + 1);
                        float n2 = __shfl_sync(0xffffffffu, edv.y, j + 2);
                        float n3 = __shfl_sync(0xffffffffu, edv.y, j + 3);
                        float2 t0 = *reinterpret_cast<const float2*>(tab + r0 * 50 + lc);
                        float2 t1 = *reinterpret_cast<const float2*>(tab + r1 * 50 + lc);
                        float2 t2 = *reinterpret_cast<const float2*>(tab + r2 * 50 + lc);
                        float2 t3 = *reinterpret_cast<const float2*>(tab + r3 * 50 + lc);
                        a0 = fmaf(n0, t0.x, a0); a1 = fmaf(n0, t0.y, a1);
                        a0 = fmaf(n1, t1.x, a0); a1 = fmaf(n1, t1.y, a1);
                        a0 = fmaf(n2, t2.x, a0); a1 = fmaf(n2, t2.y, a1);
                        a0 = fmaf(n3, t3.x, a0); a1 = fmaf(n3, t3.y, a1);
                    }
                    for (; j < jend; j++) {
                        int rr = __shfl_sync(0xffffffffu, rowm, j);
                        float nm = __shfl_sync(0xffffffffu, edv.y, j);
                        float2 tv = *reinterpret_cast<const float2*>(tab + rr * 50 + lc);
                        a0 = fmaf(nm, tv.x, a0);
                        a1 = fmaf(nm, tv.y, a1);
                    }
                    e = lim;
                }

                if (alane) {
                    float2* op = reinterpret_cast<float2*>(
                        out + (size_t)vrow * D + cbase + lc);
                    float2 p = *op;
                    p.x += a0;
                    p.y += a1;
                    *op = p;
                    sS0 += p.x; sS1 += p.y;
                    sQ0 += p.x * p.x; sQ1 += p.y * p.y;
                }
            }
        }

        // CTA BN reduce (reuse tab region after all warps are done) -> atomics
        __syncthreads();
        if (alane) {
            tab[team * 50 + lane * 2]     = sS0;
            tab[team * 50 + lane * 2 + 1] = sS1;
            tab[800 + team * 50 + lane * 2]     = sQ0;
            tab[800 + team * 50 + lane * 2 + 1] = sQ1;
        }
        __syncthreads();
        if (tid < 50) {
            float ts = 0.f, tq = 0.f;
            #pragma unroll
            for (int w = 0; w < 16; w++) {
                ts += tab[w * 50 + tid];
                tq += tab[800 + w * 50 + tid];
            }
            atomicAdd(&g_sum[cbase + tid], ts);
            atomicAdd(&g_sumsq[cbase + tid], tq);
        }
    }
    grid_bar();

    // ---------------- phase 6: BN normalize ----------------
    {
        float invV = 1.f / (float)V;
        if (tid < D) {
            float mean = g_sum[tid] * invV;
            float var = g_sumsq[tid] * invV - mean * mean;
            float sc = bn_w[tid] * rsqrtf(var + 1e-5f);
            rs[tid] = sc;
            fred[tid] = bn_b[tid] - mean * sc;
        }
        __syncthreads();
        int r0 = cta * CHUNK;
        for (int i = tid; i < CHUNK * 50; i += THREADS) {
            int r = r0 + i / 50;
            if (r < V) {
                int c4 = (i % 50) * 4;
                float4* p = reinterpret_cast<float4*>(out + (size_t)r * D + c4);
                float4 v = *p;
                v.x = v.x * rs[c4]     + fred[c4];
                v.y = v.y * rs[c4 + 1] + fred[c4 + 1];
                v.z = v.z * rs[c4 + 2] + fred[c4 + 2];
                v.w = v.w * rs[c4 + 3] + fred[c4 + 3];
                *p = v;
            }
        }
    }
}

// ============================================================================
extern "C" void kernel_launch(void* const* d_in, const int* in_sizes, int n_in,
                              void* d_out, int out_size) {
    const float* x         = (const float*)d_in[0];
    const float* rel_repr  = (const float*)d_in[1];
    const float* edge_norm = (const float*)d_in[2];
    const float* in_w      = (const float*)d_in[3];
    const float* out_w     = (const float*)d_in[4];
    const float* loop_w    = (const float*)d_in[5];
    const float* w_rel     = (const float*)d_in[6];
    const float* loop_rel  = (const float*)d_in[7];
    const float* bias      = (const float*)d_in[8];
    const float* bn_w      = (const float*)d_in[9];
    const float* bn_b      = (const float*)d_in[10];
    const int*   edge_type = (const int*)d_in[11];
    const int*   dst       = (const int*)d_in[12];
    float* out = (float*)d_out;

    int V = in_sizes[0] / D;   // 100000
    int E = in_sizes[2];       // 1000000

    // smem: max(GEMM bf16 buffers = 207,360 B, Mtab chunk = 189,600 B)
    size_t smem = (size_t)(2 * KROWS * PITCH + 2 * TILE * PITCH) * 2;
    cudaFuncSetAttribute(mega_kernel,
                         cudaFuncAttributeMaxDynamicSharedMemorySize, (int)smem);

    mega_kernel<<<NCTA, THREADS, smem>>>(x, rel_repr, edge_norm, in_w, out_w,
                                         loop_w, w_rel, loop_rel, bias, bn_w,
                                         bn_b, edge_type, dst, out, V, E);
}